// round 13
// baseline (speedup 1.0000x reference)
#include <cuda_runtime.h>
#include <math.h>
#include <stdint.h>

#define BATCH 64
#define TT    2048
#define HH    128
#define DIN   108
#define LL    37

#define BG    4      // batches per cluster
#define CSZ   4      // CTAs per cluster
#define UPC   32     // hidden units per CTA

#define WREG  112    // k-range held in registers (permuted order)
#define WSMK  16     // k-range held in smem

#define ACC1_OFF 1
#define ACC3_OFF 65
#define ACT_OFF  129
#define PRED_OFF (129 + BATCH*HH)

// ---------------- device scratch (static; no runtime allocation) ----------------
__device__ __align__(16) float g_pre[2][TT][512][BATCH];   // x@Wih0^T + (bih0+bhh0)
__device__ __align__(16) float g_hf[2][HH][BATCH];

__device__ __forceinline__ float sigf(float x)    { return 1.0f / (1.0f + __expf(-x)); }
__device__ __forceinline__ float tanhfast(float x){ return 2.0f / (1.0f + __expf(-2.0f * x)) - 1.0f; }

__device__ __forceinline__ unsigned long long pack2(float x, float y) {
    unsigned long long r;
    asm("mov.b64 %0, {%1, %2};" : "=l"(r) : "f"(x), "f"(y));
    return r;
}
__device__ __forceinline__ void fma2(unsigned long long& acc, unsigned long long w2,
                                     unsigned long long v2) {
    asm("fma.rn.f32x2 %0, %1, %2, %0;" : "+l"(acc) : "l"(w2), "l"(v2));
}
// async remote store, tx-tracked on the destination CTA's (phase-selected) mbarrier
__device__ __forceinline__ void st_async_f32(uint32_t saddr, uint32_t mbaddr,
                                             uint32_t rk, float v) {
    uint32_t ra, rb;
    asm volatile("mapa.shared::cluster.u32 %0, %1, %2;" : "=r"(ra) : "r"(saddr), "r"(rk));
    asm volatile("mapa.shared::cluster.u32 %0, %1, %2;" : "=r"(rb) : "r"(mbaddr), "r"(rk));
    asm volatile("st.async.shared::cluster.mbarrier::complete_tx::bytes.b32 [%0], %1, [%2];"
                 :: "r"(ra), "r"(__float_as_uint(v)), "r"(rb) : "memory");
}
__device__ __forceinline__ void mbar_expect_tx(uint32_t mbaddr, uint32_t tx) {
    asm volatile("mbarrier.arrive.expect_tx.shared.b64 _, [%0], %1;"
                 :: "r"(mbaddr), "r"(tx) : "memory");
}
__device__ __forceinline__ void mbar_wait_parity(uint32_t mbaddr, uint32_t parity) {
    uint32_t done;
    asm volatile(
        "{\n\t.reg .pred p;\n\t"
        "mbarrier.try_wait.parity.acquire.cluster.shared::cta.b64 p, [%1], %2;\n\t"
        "selp.b32 %0, 1, 0, p;\n\t}"
        : "=r"(done) : "r"(mbaddr), "r"(parity) : "memory");
    if (!done) {
        asm volatile(
            "{\n\t.reg .pred p;\n\t"
            "WL_%=:\n\t"
            "mbarrier.try_wait.parity.acquire.cluster.shared::cta.b64 p, [%0], %1, 0x989680;\n\t"
            "@p bra.uni WD_%=;\n\t"
            "bra.uni WL_%=;\n\t"
            "WD_%=:\n\t}"
            :: "r"(mbaddr), "r"(parity) : "memory");
    }
}
#define CLUSTER_SYNC() do { \
    asm volatile("barrier.cluster.arrive.aligned;" ::: "memory"); \
    asm volatile("barrier.cluster.wait.aligned;"   ::: "memory"); \
} while (0)
#define BAR_SYNC(id, cnt) asm volatile("bar.sync %0, %1;" :: "r"(id), "r"(cnt) : "memory")

// ==================================================================
// Kernel 1: precompute gate inputs  pre[br][t][row][b]
// ==================================================================
#define GX_XS 0
#define GX_WS (DIN*68)
#define GX_BS (GX_WS + 64*113)
#define GEMM_SMEM_FLOATS (GX_BS + 64)

__global__ void __launch_bounds__(128)
pre_gemm_kernel(const float* __restrict__ xl, const float* __restrict__ xr,
                const float* __restrict__ xo,
                const int* __restrict__ isl, const int* __restrict__ isr,
                const float* __restrict__ Wl, const float* __restrict__ bil, const float* __restrict__ bhl,
                const float* __restrict__ Wr, const float* __restrict__ bir, const float* __restrict__ bhr)
{
    extern __shared__ float sg[];
    float* xs  = sg + GX_XS;
    float* Wsm = sg + GX_WS;
    float* bsm = sg + GX_BS;

    const int rb  = blockIdx.x;
    const int t   = blockIdx.y;
    const int br  = blockIdx.z;
    const int tid = threadIdx.x;

    const float* xh  = br ? xr  : xl;
    const int*   ish = br ? isr : isl;
    const float* W   = br ? Wr  : Wl;
    const float* bi  = br ? bir : bil;
    const float* bh  = br ? bhr : bhl;

    for (int i = tid; i < BATCH * DIN; i += 128) {
        int b = i / DIN, k = i - b * DIN;
        float v;
        if (k < 99) v = xh[(b * TT + t) * 99 + k] * ((ish[b] != 0) ? 1.0f : 0.0f);
        else        v = xo[(b * TT + t) * 9 + (k - 99)];
        xs[k * 68 + b] = v;
    }
    for (int i = tid; i < 64 * DIN; i += 128) {
        int lr = i / DIN, k = i - lr * DIN;
        Wsm[lr * 113 + k] = W[(rb * 64 + lr) * DIN + k];
    }
    if (tid < 64) bsm[tid] = bi[rb * 64 + tid] + bh[rb * 64 + tid];
    __syncthreads();

    const int rg = tid >> 4;
    const int b4 = (tid & 15) * 4;

    float4 acc[8];
    #pragma unroll
    for (int j = 0; j < 8; ++j) {
        float bb = bsm[rg * 8 + j];
        acc[j] = make_float4(bb, bb, bb, bb);
    }
    #pragma unroll 4
    for (int k = 0; k < DIN; ++k) {
        float4 xv = *(const float4*)&xs[k * 68 + b4];
        #pragma unroll
        for (int j = 0; j < 8; ++j) {
            float w = Wsm[(rg * 8 + j) * 113 + k];
            acc[j].x += w * xv.x; acc[j].y += w * xv.y;
            acc[j].z += w * xv.z; acc[j].w += w * xv.w;
        }
    }
    #pragma unroll
    for (int j = 0; j < 8; ++j) {
        int row = rb * 64 + rg * 8 + j;
        *(float4*)&g_pre[br][t][row][b4] = acc[j];
    }
}

// ==================================================================
// Kernel 2: cluster-parallel wavefront recurrence with local/remote k-split.
// Permuted k-order: thread's k index j maps to unit (cu0+j)&127, so
// j in [0,UPC) = OWN units (read from local hloc, no barrier needed);
// j in [UPC,128) = remote units (read from DSMEM bufs after mbar wait).
// Own h goes to hloc via st.shared; only 3 remote ranks get st.async
// (tx = 1536B per buffer per phase). Double-buffered mbarriers as in R12.
// ==================================================================
#define WS_OFF  0                        // ws[3][WSMK][128]
#define B1_OFF  (WS_OFF + 3*WSMK*HH)     // 128
#define H0_OFF  (B1_OFF + HH)            // 2 slots x 128 units x 4 (DSMEM-received)
#define H2_OFF  (H0_OFF + 2*HH*BG)
#define H0L_OFF (H2_OFF + 2*HH*BG)       // 2 slots x 32 own units x 4 (local)
#define H2L_OFF (H0L_OFF + 2*UPC*BG)
#define G_OFF   (H2L_OFF + 2*UPC*BG)     // g[3][128][4]
#define MB_OFF  (G_OFF + 3*HH*BG)        // 2 x u64 mbarrier (4 floats)
#define REC_SMEM_FLOATS (MB_OFF + 4)

__global__ void __launch_bounds__(384, 1) __cluster_dims__(CSZ, 1, 1)
lstm_recurrent_kernel(const float* __restrict__ Whh0_l, const float* __restrict__ Whh0_r,
                      const float* __restrict__ Wih1_l, const float* __restrict__ Whh1_l,
                      const float* __restrict__ bih1_l, const float* __restrict__ bhh1_l,
                      const float* __restrict__ Wih1_r, const float* __restrict__ Whh1_r,
                      const float* __restrict__ bih1_r, const float* __restrict__ bhh1_r,
                      const int* __restrict__ dur)
{
    extern __shared__ float sm[];
    float* wsAll  = sm + WS_OFF;
    float* b1sm   = sm + B1_OFF;
    float* h0buf  = sm + H0_OFF;    // [slot][unit(128)][b(4)]  (remote-filled)
    float* h2buf  = sm + H2_OFF;
    float* h0loc  = sm + H0L_OFF;   // [slot][own unit(32)][b(4)]
    float* h2loc  = sm + H2L_OFF;
    float* gall   = sm + G_OFF;     // [jid][row(128)][b(4)]

    const int tid = threadIdx.x;
    const int blk = blockIdx.x;
    const int cid = blk >> 2;            // cluster id 0..31
    const int br  = cid >> 4;            // branch
    const int bg0 = (cid & 15) * BG;     // first batch of group

    uint32_t rank;
    asm("mov.u32 %0, %%cluster_ctarank;" : "=r"(rank));
    const int cu0 = (int)rank * UPC;

    const float* Whh0 = br ? Whh0_r : Whh0_l;
    const float* Wih1 = br ? Wih1_r : Wih1_l;
    const float* Whh1 = br ? Whh1_r : Whh1_l;
    const float* bi1  = br ? bih1_r : bih1_l;
    const float* bh1  = br ? bhh1_r : bhh1_l;

    const int jid = tid >> 7;            // 0=L0, 1=L1a(Wih1), 2=L1b(Whh1)
    const int r   = tid & 127;           // gate-row
    const int grow = (r >> 5) * HH + cu0 + (r & 31);

    const float* mat = (jid == 0) ? Whh0 : ((jid == 1) ? Wih1 : Whh1);

    // ---- weights in PERMUTED k-order: slot j <-> unit (cu0+j)&127 ----
    float wreg[WREG];
    #pragma unroll
    for (int j = 0; j < WREG; ++j) wreg[j] = mat[grow * HH + ((cu0 + j) & 127)];
    float* wsm = wsAll + jid * WSMK * HH;
    for (int kk = 0; kk < WSMK; ++kk)
        wsm[kk * HH + r] = mat[grow * HH + ((cu0 + WREG + kk) & 127)];

    if (tid < HH) {
        int gr = (tid >> 5) * HH + cu0 + (tid & 31);
        b1sm[tid] = bi1[gr] + bh1[gr];
    }
    for (int i = tid; i < 2 * HH * BG; i += 384) { h0buf[i] = 0.0f; h2buf[i] = 0.0f; }
    for (int i = tid; i < 2 * UPC * BG; i += 384) { h0loc[i] = 0.0f; h2loc[i] = 0.0f; }

    const uint32_t mbar0 = (uint32_t)__cvta_generic_to_shared(sm + MB_OFF);
    const uint32_t mbar1 = mbar0 + 8u;
    if (tid == 0) {
        asm volatile("mbarrier.init.shared.b64 [%0], %1;" :: "r"(mbar0), "r"(1) : "memory");
        asm volatile("mbarrier.init.shared.b64 [%0], %1;" :: "r"(mbar1), "r"(1) : "memory");
        mbar_expect_tx(mbar0, 1536u);   // phase 0: h0 only, 3 remote ranks x 512B
        mbar_expect_tx(mbar1, 3072u);   // phase 1: h0 + h2
    }
    __syncthreads();
    CLUSTER_SYNC();   // barriers armed + zeros + smem weights visible before step 0

    const uint32_t h0base = (uint32_t)__cvta_generic_to_shared(h0buf);
    const uint32_t h2base = (uint32_t)__cvta_generic_to_shared(h2buf);

    const int su = (tid & 127) >> 2;     // own unit (0..31)
    const int sb = tid & 3;              // batch
    float c0 = 0.0f, c1 = 0.0f;
    const int durb = dur[bg0 + sb];

    float4 p = make_float4(0.f, 0.f, 0.f, 0.f);
    if (jid == 0) p = __ldcs((const float4*)&g_pre[br][0][grow][bg0]);

    for (int s = 0; s <= TT; ++s) {
        const bool active = (jid == 0) ? (s < TT) : (s >= 1);
        unsigned long long a01, a23;

        // ---- A: local partial (own 32 units, no barrier needed) ----
        if (active) {
            if (jid == 0) {
                a01 = pack2(p.x, p.y); a23 = pack2(p.z, p.w);
            } else if (jid == 1) {
                float bb = b1sm[r];
                a01 = pack2(bb, bb); a23 = a01;
            } else {
                a01 = 0ull; a23 = 0ull;
            }
            const float* lsrc = ((jid == 2) ? h2loc : h0loc) + ((s + 1) & 1) * (UPC * BG);
            #pragma unroll
            for (int j = 0; j < UPC; ++j) {
                ulonglong2 v = *(const ulonglong2*)&lsrc[j * BG];
                unsigned long long wp = pack2(wreg[j], wreg[j]);
                fma2(a01, wp, v.x);
                fma2(a23, wp, v.y);
            }
        } else { a01 = 0ull; a23 = 0ull; }

        // ---- B: wait for remote phase s-1, re-arm for phase s+1 ----
        if (s > 0) {
            const uint32_t mbprev = ((s - 1) & 1) ? mbar1 : mbar0;
            mbar_wait_parity(mbprev, (unsigned)(((s - 1) >> 1) & 1));
            if (tid == 0 && s + 1 <= TT) {
                uint32_t tx = ((s + 1 < TT) ? 1536u : 0u) + 1536u;
                mbar_expect_tx(mbprev, tx);
            }
        }

        // ---- C: remote partial (96 units from DSMEM bufs) ----
        if (active) {
            const float* hsrc = ((jid == 2) ? h2buf : h0buf) + ((s + 1) & 1) * (HH * BG);
            #pragma unroll
            for (int j = UPC; j < WREG; ++j) {
                int u = (cu0 + j) & 127;
                ulonglong2 v = *(const ulonglong2*)&hsrc[u * BG];
                unsigned long long wp = pack2(wreg[j], wreg[j]);
                fma2(a01, wp, v.x);
                fma2(a23, wp, v.y);
            }
            #pragma unroll 8
            for (int kk = 0; kk < WSMK; ++kk) {
                int u = (cu0 + WREG + kk) & 127;
                float w = wsm[kk * HH + r];
                unsigned long long wp = pack2(w, w);
                ulonglong2 v = *(const ulonglong2*)&hsrc[u * BG];
                fma2(a01, wp, v.x);
                fma2(a23, wp, v.y);
            }
            ((ulonglong2*)gall)[jid * HH + r] = make_ulonglong2(a01, a23);
        }

        // ---- D: per-job-group sync ----
        if (jid == 0) BAR_SYNC(1, 128);
        else          BAR_SYNC(2, 256);

        const uint32_t mbcur = (s & 1) ? mbar1 : mbar0;

        // ---- E: state updates; local store + st.async to 3 remote ranks ----
        if (tid < 128) {
            if (s < TT) {
                const float* g0 = gall;
                float ip = g0[(0  + su) * BG + sb];
                float fp = g0[(32 + su) * BG + sb];
                float gp = g0[(64 + su) * BG + sb];
                float op = g0[(96 + su) * BG + sb];
                c0 = sigf(fp) * c0 + sigf(ip) * tanhfast(gp);
                float h = sigf(op) * tanhfast(c0);
                h0loc[((s & 1) * UPC + su) * BG + sb] = h;
                uint32_t la = h0base + (uint32_t)((((s & 1) * HH + cu0 + su) * BG + sb) * 4);
                #pragma unroll
                for (uint32_t rr = 0; rr < CSZ; ++rr)
                    if (rr != rank) st_async_f32(la, mbcur, rr, h);
            }
        } else if (tid < 256) {
            if (s >= 1) {
                const float* ga = gall + 1 * HH * BG;
                const float* gb = gall + 2 * HH * BG;
                float ip = ga[(0  + su) * BG + sb] + gb[(0  + su) * BG + sb];
                float fp = ga[(32 + su) * BG + sb] + gb[(32 + su) * BG + sb];
                float gp = ga[(64 + su) * BG + sb] + gb[(64 + su) * BG + sb];
                float op = ga[(96 + su) * BG + sb] + gb[(96 + su) * BG + sb];
                c1 = sigf(fp) * c1 + sigf(ip) * tanhfast(gp);
                float h = sigf(op) * tanhfast(c1);
                h2loc[((s & 1) * UPC + su) * BG + sb] = h;
                uint32_t la = h2base + (uint32_t)((((s & 1) * HH + cu0 + su) * BG + sb) * 4);
                #pragma unroll
                for (uint32_t rr = 0; rr < CSZ; ++rr)
                    if (rr != rank) st_async_f32(la, mbcur, rr, h);
                if (s == durb) g_hf[br][cu0 + su][bg0 + sb] = h;
            }
        }

        // prefetch next step's pre-GEMM inputs
        if (jid == 0 && s + 1 < TT)
            p = __ldcs((const float4*)&g_pre[br][s + 1][grow][bg0]);

        // ---- F: hloc visibility for next iteration's local partials ----
        __syncthreads();
    }

    // drain final phase, invalidate barriers, full cluster quiesce before exit
    mbar_wait_parity((TT & 1) ? mbar1 : mbar0, (unsigned)((TT >> 1) & 1));
    __syncthreads();
    if (tid == 0) {
        asm volatile("mbarrier.inval.shared.b64 [%0];" :: "r"(mbar0) : "memory");
        asm volatile("mbarrier.inval.shared.b64 [%0];" :: "r"(mbar1) : "memory");
    }
    CLUSTER_SYNC();
}

// ==================================================================
// Kernel 3: epilogue
// ==================================================================
__global__ void __launch_bounds__(64)
epilogue_kernel(const int* __restrict__ yv,
                const float* __restrict__ wcl, const float* __restrict__ bcl,
                const float* __restrict__ wcr, const float* __restrict__ bcr,
                const float* __restrict__ Wout, const float* __restrict__ bout,
                float* __restrict__ out)
{
    __shared__ float lsum[64];
    const int b = threadIdx.x;

    float hl[HH + 2], hr[HH + 2], y3[HH];
    hl[0] = 0.0f; hl[HH + 1] = 0.0f;
    hr[0] = 0.0f; hr[HH + 1] = 0.0f;
    for (int j = 0; j < HH; ++j) {
        hl[j + 1] = g_hf[0][j][b];
        hr[j + 1] = g_hf[1][j][b];
    }
    float wl0 = wcl[0], wl1 = wcl[1], wl2 = wcl[2], bl = bcl[0];
    float wr0 = wcr[0], wr1 = wcr[1], wr2 = wcr[2], br_ = bcr[0];
    for (int j = 0; j < HH; ++j) {
        float vl = wl0 * hl[j] + wl1 * hl[j + 1] + wl2 * hl[j + 2] + bl;
        float vr = wr0 * hr[j] + wr1 * hr[j + 1] + wr2 * hr[j + 2] + br_;
        y3[j] = vl + vr;
        out[ACT_OFF + b * HH + j] = tanhf(y3[j]) * 0.1f;
    }
    float logits[LL];
    float mx = -1e30f;
    for (int l = 0; l < LL; ++l) {
        float s = bout[l];
        for (int j = 0; j < HH; ++j) s += y3[j] * Wout[l * HH + j];
        logits[l] = s;
        mx = fmaxf(mx, s);
    }
    float den = 0.0f;
    for (int l = 0; l < LL; ++l) { logits[l] = expf(logits[l] - mx); den += logits[l]; }
    float inv = 1.0f / den;
    int yb = yv[b];
    float py = 0.0f, myloss = 0.0f;
    for (int l = 0; l < LL; ++l) {
        float pql = logits[l] * inv;
        logits[l] = pql;
        out[PRED_OFF + b * LL + l] = pql;
        if (l == yb) py = pql;
    }
    for (int l = 0; l < LL; ++l) {
        float pql = logits[l];
        float lp = fmaxf(logf(pql), -100.0f);
        float lq = fmaxf(logf(1.0f - pql), -100.0f);
        myloss += (l == yb) ? lp : lq;
    }
    int rank = 0;
    for (int l = 0; l < LL; ++l) {
        if (logits[l] > py) rank++;
        else if (logits[l] == py && l < yb) rank++;
    }
    out[ACC1_OFF + b] = (rank == 0) ? 1.0f : 0.0f;
    out[ACC3_OFF + b] = (rank < 3) ? 1.0f : 0.0f;

    lsum[b] = myloss;
    __syncthreads();
    if (b == 0) {
        float s = 0.0f;
        for (int i = 0; i < BATCH; ++i) s += lsum[i];
        out[0] = -s / (float)(BATCH * LL);
    }
}

// ==================================================================
extern "C" void kernel_launch(void* const* d_in, const int* in_sizes, int n_in,
                              void* d_out, int out_size) {
    (void)in_sizes; (void)n_in; (void)out_size;
    cudaFuncSetAttribute(pre_gemm_kernel, cudaFuncAttributeMaxDynamicSharedMemorySize,
                         GEMM_SMEM_FLOATS * (int)sizeof(float));
    cudaFuncSetAttribute(lstm_recurrent_kernel, cudaFuncAttributeMaxDynamicSharedMemorySize,
                         REC_SMEM_FLOATS * (int)sizeof(float));

    const float* xl  = (const float*)d_in[0];
    const float* xr  = (const float*)d_in[1];
    const float* xo  = (const float*)d_in[2];
    const int*   yv  = (const int*)d_in[3];
    const int*   isl = (const int*)d_in[4];
    const int*   isr = (const int*)d_in[5];
    const int*   dur = (const int*)d_in[6];

    pre_gemm_kernel<<<dim3(8, TT, 2), 128, GEMM_SMEM_FLOATS * sizeof(float)>>>(
        xl, xr, xo, isl, isr,
        (const float*)d_in[7],  (const float*)d_in[9],  (const float*)d_in[10],
        (const float*)d_in[15], (const float*)d_in[17], (const float*)d_in[18]);

    lstm_recurrent_kernel<<<128, 384, REC_SMEM_FLOATS * sizeof(float)>>>(
        (const float*)d_in[8],  (const float*)d_in[16],
        (const float*)d_in[11], (const float*)d_in[12],
        (const float*)d_in[13], (const float*)d_in[14],
        (const float*)d_in[19], (const float*)d_in[20],
        (const float*)d_in[21], (const float*)d_in[22],
        dur);

    epilogue_kernel<<<1, 64>>>(
        yv,
        (const float*)d_in[23], (const float*)d_in[24],
        (const float*)d_in[25], (const float*)d_in[26],
        (const float*)d_in[27], (const float*)d_in[28],
        (float*)d_out);
}